// round 5
// baseline (speedup 1.0000x reference)
#include <cuda_runtime.h>
#include <cstdint>
#include <cstddef>

// E3Hamiltonian: block-diagonal per-edge transform, ROW=282 floats per edge.
// out[n, off + p*m + j] = sum_mm cg[j*m+mm] * in[n, off + p*m + mm]

#define ROW 282
#define TILE 32                            // 600000 % 32 == 0
#define NWC 16                             // compute warps
#define THREADS ((NWC + 1) * 32)           // + 1 producer warp = 544
#define NIN 3
#define NOUT 2
#define TILE_FLOATS (TILE * ROW)           // 9024
#define TILE_BYTES  (TILE_FLOATS * 4)      // 36096
#define CG_TOTAL 1104
#define SMEM_TOTAL ((NIN + NOUT) * TILE_BYTES + CG_TOTAL * 4 + 64)  // 184960

// ---------------- PTX helpers ----------------
__device__ __forceinline__ uint32_t smem_u32(const void* p) {
    return (uint32_t)__cvta_generic_to_shared(p);
}
__device__ __forceinline__ void mbar_init(uint32_t mbar, uint32_t count) {
    asm volatile("mbarrier.init.shared.b64 [%0], %1;" :: "r"(mbar), "r"(count) : "memory");
}
__device__ __forceinline__ void mbar_expect_tx(uint32_t mbar, uint32_t bytes) {
    asm volatile("mbarrier.arrive.expect_tx.shared::cta.b64 _, [%0], %1;"
                 :: "r"(mbar), "r"(bytes) : "memory");
}
__device__ __forceinline__ void mbar_arrive(uint32_t mbar) {
    asm volatile("mbarrier.arrive.release.cta.shared::cta.b64 _, [%0];"
                 :: "r"(mbar) : "memory");
}
__device__ __forceinline__ void mbar_wait(uint32_t mbar, uint32_t parity) {
    asm volatile(
        "{\n\t.reg .pred P;\n\t"
        "WL_%=:\n\t"
        "mbarrier.try_wait.parity.acquire.cta.shared::cta.b64 P, [%0], %1, 0x989680;\n\t"
        "@P bra.uni WD_%=;\n\t"
        "bra.uni WL_%=;\n\t"
        "WD_%=:\n\t}"
        :: "r"(mbar), "r"(parity) : "memory");
}
__device__ __forceinline__ void tma_load_1d(uint32_t dst_smem, const void* src_gmem,
                                            uint32_t bytes, uint32_t mbar) {
    asm volatile(
        "cp.async.bulk.shared::cta.global.mbarrier::complete_tx::bytes [%0], [%1], %2, [%3];"
        :: "r"(dst_smem), "l"(src_gmem), "r"(bytes), "r"(mbar) : "memory");
}
__device__ __forceinline__ void tma_store_1d(void* dst_gmem, uint32_t src_smem, uint32_t bytes) {
    asm volatile(
        "cp.async.bulk.global.shared::cta.bulk_group [%0], [%1], %2;"
        :: "l"(dst_gmem), "r"(src_smem), "r"(bytes) : "memory");
}
__device__ __forceinline__ void tma_commit() {
    asm volatile("cp.async.bulk.commit_group;" ::: "memory");
}
__device__ __forceinline__ void tma_wait_group_1() {
    asm volatile("cp.async.bulk.wait_group 1;" ::: "memory");
}
__device__ __forceinline__ void tma_wait_all() {
    asm volatile("cp.async.bulk.wait_group 0;" ::: "memory");
}
__device__ __forceinline__ void fence_async_shared() {
    asm volatile("fence.proxy.async.shared::cta;" ::: "memory");
}

// ---------------- compute ----------------
// m x m matvec restricted to output rows [J0,J1): read M inputs, write J1-J0
// outputs. in/out are DIFFERENT buffers -> no hazard, arbitrary splits legal.
template <int M, int MP, int J0, int J1>
__device__ __forceinline__ void taskr(const float* __restrict__ in_row,
                                      float* __restrict__ out_row,
                                      const float* __restrict__ cg, int col) {
    float in[M];
#pragma unroll
    for (int mm = 0; mm < M; mm++) in[mm] = in_row[col + mm];
#pragma unroll
    for (int j = J0; j < J1; j++) {
        const float4* c4 = reinterpret_cast<const float4*>(cg + j * MP);
        float acc = 0.f;
#pragma unroll
        for (int k = 0; k < MP / 4; k++) {
            float4 c = c4[k];
            if (4 * k + 0 < M) acc += c.x * in[4 * k + 0];
            if (4 * k + 1 < M) acc += c.y * in[4 * k + 1];
            if (4 * k + 2 < M) acc += c.z * in[4 * k + 2];
            if (4 * k + 3 < M) acc += c.w * in[4 * k + 3];
        }
        out_row[col + j] = acc;
    }
}

// cg smem bases: ss=0(m1,mp4) sp=4(m3,mp4) sd=16(m5,mp8) pp=56(m9,mp12)
//                pd=164(m15,mp16) dd=404(m25,mp28)
// 16-warp balanced schedule, ~280 padded FFMA per warp (max 288).
__device__ __forceinline__ void compute_row(const float* __restrict__ i,
                                            float* __restrict__ o,
                                            const float* __restrict__ g, int w) {
    const float* ss = g + 0;  const float* sp = g + 4;   const float* sd = g + 16;
    const float* pp = g + 56; const float* pd = g + 164; const float* dd = g + 404;
    switch (w) {
        case 0:  taskr<15,16,0,15>(i,o,pd,117); taskr<9,12,0,5>(i,o,pp,63); break;
        case 1:  taskr<15,16,0,15>(i,o,pd,132); taskr<9,12,5,9>(i,o,pp,63); break;
        case 2:  taskr<15,16,0,15>(i,o,pd,147); taskr<9,12,0,5>(i,o,pp,72); break;
        case 3:  taskr<15,16,0,15>(i,o,pd,162); taskr<9,12,5,9>(i,o,pp,72); break;
        case 4:  taskr<15,16,0,15>(i,o,pd,177); taskr<9,12,0,5>(i,o,pp,81); break;
        case 5:  taskr<15,16,0,15>(i,o,pd,192); taskr<9,12,5,9>(i,o,pp,81); break;
        case 6:  taskr<25,28,0,10>(i,o,dd,207); break;
        case 7:  taskr<25,28,10,20>(i,o,dd,207); break;
        case 8:  taskr<25,28,20,25>(i,o,dd,207); taskr<25,28,0,5>(i,o,dd,232); break;
        case 9:  taskr<25,28,5,15>(i,o,dd,232); break;
        case 10: taskr<25,28,15,25>(i,o,dd,232); break;
        case 11: taskr<25,28,0,10>(i,o,dd,257); break;
        case 12: taskr<25,28,10,20>(i,o,dd,257); break;
        case 13: taskr<25,28,20,25>(i,o,dd,257);
                 taskr<5,8,0,5>(i,o,sd,33); taskr<5,8,0,5>(i,o,sd,38);
                 taskr<3,4,0,3>(i,o,sp,6);  taskr<3,4,0,3>(i,o,sp,9);
                 taskr<3,4,0,3>(i,o,sp,24); taskr<3,4,0,3>(i,o,sp,27);
                 taskr<3,4,0,3>(i,o,sp,30); taskr<1,4,0,1>(i,o,ss,0); break;
        case 14: taskr<9,12,0,9>(i,o,pp,90); taskr<9,12,0,9>(i,o,pp,99);
                 taskr<5,8,0,5>(i,o,sd,43);
                 taskr<1,4,0,1>(i,o,ss,1); taskr<1,4,0,1>(i,o,ss,2); break;
        default: taskr<9,12,0,9>(i,o,pp,108);
                 taskr<5,8,0,5>(i,o,sd,48); taskr<5,8,0,5>(i,o,sd,53);
                 taskr<5,8,0,5>(i,o,sd,58);
                 taskr<3,4,0,3>(i,o,sp,12); taskr<3,4,0,3>(i,o,sp,15);
                 taskr<3,4,0,3>(i,o,sp,18); taskr<3,4,0,3>(i,o,sp,21);
                 taskr<1,4,0,1>(i,o,ss,3);  taskr<1,4,0,1>(i,o,ss,4);
                 taskr<1,4,0,1>(i,o,ss,5); break;
    }
}

__device__ __forceinline__ void fill_cg(float* __restrict__ dst, const float* __restrict__ src,
                                        int m, int mp, int tid) {
    int total = m * mp;
    for (int i = tid; i < total; i += THREADS) {
        int row = i / mp, c = i - row * mp;
        dst[i] = (c < m) ? src[row * m + c] : 0.f;
    }
}

extern __shared__ __align__(128) unsigned char dynsmem[];

__global__ __launch_bounds__(THREADS, 1)
void e3h_kernel(const float* __restrict__ ef,
                const float* __restrict__ cg_ss, const float* __restrict__ cg_sp,
                const float* __restrict__ cg_sd, const float* __restrict__ cg_pp,
                const float* __restrict__ cg_pd, const float* __restrict__ cg_dd,
                float* __restrict__ out, int n, int ntiles) {
    float* ibuf = reinterpret_cast<float*>(dynsmem);            // 3 in tiles
    float* obuf = ibuf + NIN * TILE_FLOATS;                     // 2 out tiles
    float* s_cg = obuf + NOUT * TILE_FLOATS;
    unsigned long long* mb = reinterpret_cast<unsigned long long*>(s_cg + CG_TOTAL);
    // mb[0..2]=full_in  mb[3..4]=done  mb[5..6]=freed

    const int tid = threadIdx.x;
    const int lane = tid & 31;
    const int warp = tid >> 5;

    fill_cg(s_cg + 0,   cg_ss, 1, 4,  tid);
    fill_cg(s_cg + 4,   cg_sp, 3, 4,  tid);
    fill_cg(s_cg + 16,  cg_sd, 5, 8,  tid);
    fill_cg(s_cg + 56,  cg_pp, 9, 12, tid);
    fill_cg(s_cg + 164, cg_pd, 15, 16, tid);
    fill_cg(s_cg + 404, cg_dd, 25, 28, tid);

    uint32_t full_b[NIN], in_a[NIN], done_b[NOUT], freed_b[NOUT], out_a[NOUT];
#pragma unroll
    for (int b = 0; b < NIN; b++) {
        full_b[b] = smem_u32(mb + b);
        in_a[b]   = smem_u32(ibuf + b * TILE_FLOATS);
    }
#pragma unroll
    for (int b = 0; b < NOUT; b++) {
        done_b[b]  = smem_u32(mb + NIN + b);
        freed_b[b] = smem_u32(mb + NIN + NOUT + b);
        out_a[b]   = smem_u32(obuf + b * TILE_FLOATS);
    }
    if (tid == 0) {
#pragma unroll
        for (int b = 0; b < NIN; b++) mbar_init(full_b[b], 1);
#pragma unroll
        for (int b = 0; b < NOUT; b++) { mbar_init(done_b[b], NWC); mbar_init(freed_b[b], 1); }
    }
    __syncthreads();

    const int bid = blockIdx.x;
    const int grid = gridDim.x;
    const int cnt = (bid < ntiles) ? (ntiles - bid + grid - 1) / grid : 0;

    if (warp == NWC) {
        // -------- producer (single thread) --------
        if (lane == 0) {
            const int npro = (cnt < NIN) ? cnt : NIN;
            for (int p = 0; p < npro; p++) {
                mbar_expect_tx(full_b[p], TILE_BYTES);
                tma_load_1d(in_a[p], ef + ((size_t)bid + (size_t)p * grid) * TILE_FLOATS,
                            TILE_BYTES, full_b[p]);
            }
            for (int k = 0; k < cnt; k++) {
                const int ob = k & 1;
                mbar_wait(done_b[ob], (k >> 1) & 1);    // all 16 warps done tile k
                fence_async_shared();
                const size_t tile = (size_t)bid + (size_t)k * grid;
                tma_store_1d(out + tile * TILE_FLOATS, out_a[ob], TILE_BYTES);
                tma_commit();
                if (k + NIN < cnt) {                    // in-buf k%3 just freed
                    const int ib = k % NIN;
                    mbar_expect_tx(full_b[ib], TILE_BYTES);
                    tma_load_1d(in_a[ib], ef + (tile + (size_t)NIN * grid) * TILE_FLOATS,
                                TILE_BYTES, full_b[ib]);
                }
                if (k >= 1) {
                    tma_wait_group_1();                 // store k-1 drained
                    mbar_arrive(freed_b[(k - 1) & 1]);  // out-buf (k-1)&1 reusable (tile k+1)
                }
            }
            tma_wait_all();
        }
    } else {
        // -------- 16 balanced compute warps --------
        for (int k = 0; k < cnt; k++) {
            const int ib = k % NIN, ob = k & 1;
            mbar_wait(full_b[ib], (k / NIN) & 1);
            if (k >= 2) mbar_wait(freed_b[ob], ((k - 2) >> 1) & 1);
            compute_row(ibuf + ib * TILE_FLOATS + lane * ROW,
                        obuf + ob * TILE_FLOATS + lane * ROW, s_cg, warp);
            __syncwarp();
            if (lane == 0) mbar_arrive(done_b[ob]);
        }
    }

    // ---- remainder (none for this dataset; generic safety) ----
    const int rem = n - ntiles * TILE;
    if (rem > 0) {
        __syncthreads();
        if (bid == 0) {
            const size_t base = (size_t)ntiles * TILE_FLOATS;
            const int cntf = rem * ROW;
            for (int i = tid; i < cntf; i += THREADS) ibuf[i] = ef[base + i];
            __syncthreads();
            if (warp < NWC && lane < rem)
                compute_row(ibuf + lane * ROW, obuf + lane * ROW, s_cg, warp);
            __syncthreads();
            for (int i = tid; i < cntf; i += THREADS) out[base + i] = obuf[i];
        }
    }
}

extern "C" void kernel_launch(void* const* d_in, const int* in_sizes, int n_in,
                              void* d_out, int out_size) {
    const float* ef    = (const float*)d_in[0];
    const float* cg_ss = (const float*)d_in[1];
    const float* cg_sp = (const float*)d_in[2];
    const float* cg_sd = (const float*)d_in[3];
    const float* cg_pp = (const float*)d_in[4];
    const float* cg_pd = (const float*)d_in[5];
    const float* cg_dd = (const float*)d_in[6];
    float* out = (float*)d_out;

    int n = in_sizes[0] / ROW;
    int ntiles = n / TILE;

    int sms = 148;
    cudaDeviceGetAttribute(&sms, cudaDevAttrMultiProcessorCount, 0);
    int grid = sms;                     // 1 CTA/SM (185KB smem)
    if (ntiles > 0 && grid > ntiles) grid = ntiles;
    if (grid < 1) grid = 1;

    cudaFuncSetAttribute(e3h_kernel, cudaFuncAttributeMaxDynamicSharedMemorySize, SMEM_TOTAL);
    e3h_kernel<<<grid, THREADS, SMEM_TOTAL>>>(ef, cg_ss, cg_sp, cg_sd, cg_pp, cg_pd, cg_dd,
                                              out, n, ntiles);
}

// round 6
// speedup vs baseline: 1.2553x; 1.2553x over previous
#include <cuda_runtime.h>
#include <cstdint>
#include <cstddef>

// E3Hamiltonian: block-diagonal per-edge transform, ROW=282 floats per edge.
// out[n, off + p*m + j] = sum_mm cg[j*m+mm] * in[n, off + p*m + mm]
// Blocks: ss(off0,np6,m1) sp(off6,np9,m3) sd(off33,np6,m5)
//         pp(off63,np6,m9) pd(off117,np6,m15) dd(off207,np3,m25)

#define ROW 282
#define TILE 32
#define THREADS 256
#define TILE_FLOATS (TILE * ROW)          // 9024
#define TILE_BYTES  (TILE_FLOATS * 4)     // 36096
#define CG_TOTAL 1104
#define SMEM_TOTAL (2 * TILE_BYTES + CG_TOTAL * 4 + 16)  // 76624 B -> 2 CTAs/SM

// ---------------- PTX helpers ----------------
__device__ __forceinline__ uint32_t smem_u32(const void* p) {
    return (uint32_t)__cvta_generic_to_shared(p);
}
__device__ __forceinline__ void mbar_init(uint32_t mbar, uint32_t count) {
    asm volatile("mbarrier.init.shared.b64 [%0], %1;" :: "r"(mbar), "r"(count) : "memory");
}
__device__ __forceinline__ void mbar_expect_tx(uint32_t mbar, uint32_t bytes) {
    asm volatile("mbarrier.arrive.expect_tx.shared::cta.b64 _, [%0], %1;"
                 :: "r"(mbar), "r"(bytes) : "memory");
}
__device__ __forceinline__ void mbar_wait(uint32_t mbar, uint32_t parity) {
    asm volatile(
        "{\n\t.reg .pred P;\n\t"
        "WL_%=:\n\t"
        "mbarrier.try_wait.parity.acquire.cta.shared::cta.b64 P, [%0], %1, 0x989680;\n\t"
        "@P bra.uni WD_%=;\n\t"
        "bra.uni WL_%=;\n\t"
        "WD_%=:\n\t}"
        :: "r"(mbar), "r"(parity) : "memory");
}
__device__ __forceinline__ void tma_load_1d(uint32_t dst_smem, const void* src_gmem,
                                            uint32_t bytes, uint32_t mbar) {
    asm volatile(
        "cp.async.bulk.shared::cta.global.mbarrier::complete_tx::bytes [%0], [%1], %2, [%3];"
        :: "r"(dst_smem), "l"(src_gmem), "r"(bytes), "r"(mbar) : "memory");
}
__device__ __forceinline__ void tma_store_1d(void* dst_gmem, uint32_t src_smem, uint32_t bytes) {
    asm volatile(
        "cp.async.bulk.global.shared::cta.bulk_group [%0], [%1], %2;"
        :: "l"(dst_gmem), "r"(src_smem), "r"(bytes) : "memory");
}
__device__ __forceinline__ void tma_commit() {
    asm volatile("cp.async.bulk.commit_group;" ::: "memory");
}
__device__ __forceinline__ void tma_wait_all() {
    asm volatile("cp.async.bulk.wait_group 0;" ::: "memory");
}
__device__ __forceinline__ void fence_async_shared() {
    asm volatile("fence.proxy.async.shared::cta;" ::: "memory");
}

// ---------------- compute ----------------
// m x m matvec, in place on this lane's row, outer-product order:
// acc[j] (registers, j = output) accumulate over streamed mm. Consecutive
// updates to acc[j] are M instructions apart -> FFMA chains fully pipelined.
// cgT layout: cgT[mm * JP + j], j padded to JP (multiple of 4), zero-filled.
template <int M, int JP>
__device__ __forceinline__ void task(float* __restrict__ r,
                                     const float* __restrict__ cgT, int col) {
    float acc[M];
#pragma unroll
    for (int j = 0; j < M; j++) acc[j] = 0.f;
#pragma unroll
    for (int mm = 0; mm < M; mm++) {
        const float x = r[col + mm];
        const float4* c4 = reinterpret_cast<const float4*>(cgT + mm * JP);
#pragma unroll
        for (int k = 0; k < JP / 4; k++) {
            float4 c = c4[k];
            if (4 * k + 0 < M) acc[4 * k + 0] += c.x * x;
            if (4 * k + 1 < M) acc[4 * k + 1] += c.y * x;
            if (4 * k + 2 < M) acc[4 * k + 2] += c.z * x;
            if (4 * k + 3 < M) acc[4 * k + 3] += c.w * x;
        }
    }
#pragma unroll
    for (int j = 0; j < M; j++) r[col + j] = acc[j];
}

// warp-partitioned task dispatch; warps own disjoint column ranges, lane = edge.
// cgT smem bases: ss=0(jp4) sp=4(jp4) sd=16(jp8) pp=56(jp12) pd=164(jp16) dd=404(jp28)
__device__ __forceinline__ void compute_row(float* __restrict__ r,
                                            const float* __restrict__ s_cg, int warp) {
    switch (warp) {
        case 0: task<25, 28>(r, s_cg + 404, 207); break;
        case 1: task<25, 28>(r, s_cg + 404, 232); break;
        case 2: task<25, 28>(r, s_cg + 404, 257); break;
        case 3: task<15, 16>(r, s_cg + 164, 117);
                task<15, 16>(r, s_cg + 164, 132); break;
        case 4: task<15, 16>(r, s_cg + 164, 147);
                task<15, 16>(r, s_cg + 164, 162); break;
        case 5: task<15, 16>(r, s_cg + 164, 177);
                task<15, 16>(r, s_cg + 164, 192); break;
        case 6: {
#pragma unroll
            for (int p = 0; p < 5; p++) task<9, 12>(r, s_cg + 56, 63 + 9 * p);
            break;
        }
        default: {  // warp 7
            task<9, 12>(r, s_cg + 56, 108);
#pragma unroll
            for (int p = 0; p < 6; p++) task<5, 8>(r, s_cg + 16, 33 + 5 * p);
#pragma unroll
            for (int p = 0; p < 9; p++) task<3, 4>(r, s_cg + 4, 6 + 3 * p);
#pragma unroll
            for (int p = 0; p < 6; p++) task<1, 4>(r, s_cg + 0, p);
            break;
        }
    }
}

// transpose-fill: dst[mm*jp + j] = src[j*m + mm], zero-pad j >= m
__device__ __forceinline__ void fill_cg_T(float* __restrict__ dst, const float* __restrict__ src,
                                          int m, int jp, int tid) {
    int total = m * jp;
    for (int i = tid; i < total; i += THREADS) {
        int mm = i / jp, j = i - mm * jp;
        dst[i] = (j < m) ? src[j * m + mm] : 0.f;
    }
}

extern __shared__ __align__(128) unsigned char dynsmem[];

__global__ __launch_bounds__(THREADS, 2)
void e3h_kernel(const float* __restrict__ ef,
                const float* __restrict__ cg_ss, const float* __restrict__ cg_sp,
                const float* __restrict__ cg_sd, const float* __restrict__ cg_pp,
                const float* __restrict__ cg_pd, const float* __restrict__ cg_dd,
                float* __restrict__ out, int n, int ntiles) {
    float* buf0 = reinterpret_cast<float*>(dynsmem);
    float* buf1 = buf0 + TILE_FLOATS;
    float* s_cg = buf1 + TILE_FLOATS;
    unsigned long long* mb = reinterpret_cast<unsigned long long*>(s_cg + CG_TOTAL);

    const int tid = threadIdx.x;
    const int lane = tid & 31;
    const int warp = tid >> 5;

    // CG -> smem, TRANSPOSED (rows = mm, cols = j padded); mbarrier init
    fill_cg_T(s_cg + 0,   cg_ss, 1, 4,  tid);
    fill_cg_T(s_cg + 4,   cg_sp, 3, 4,  tid);
    fill_cg_T(s_cg + 16,  cg_sd, 5, 8,  tid);
    fill_cg_T(s_cg + 56,  cg_pp, 9, 12, tid);
    fill_cg_T(s_cg + 164, cg_pd, 15, 16, tid);
    fill_cg_T(s_cg + 404, cg_dd, 25, 28, tid);

    const uint32_t mbad0 = smem_u32(mb);
    const uint32_t mbad1 = smem_u32(mb + 1);
    const uint32_t sb0 = smem_u32(buf0);
    const uint32_t sb1 = smem_u32(buf1);
    if (tid == 0) { mbar_init(mbad0, 1); mbar_init(mbad1, 1); }
    __syncthreads();

    const int bid = blockIdx.x;
    const int grid = gridDim.x;
    const int cnt = (bid < ntiles) ? (ntiles - bid + grid - 1) / grid : 0;

    if (cnt > 0 && tid == 0) {
        mbar_expect_tx(mbad0, TILE_BYTES);
        tma_load_1d(sb0, ef + (size_t)bid * TILE_FLOATS, TILE_BYTES, mbad0);
    }

    for (int k = 0; k < cnt; k++) {
        const size_t tile = (size_t)bid + (size_t)k * grid;
        if (tid == 0 && k + 1 < cnt) {
            // buffer (k+1)&1 was last read by store of tile k-1 -> drain stores first
            tma_wait_all();
            const uint32_t mbn = ((k + 1) & 1) ? mbad1 : mbad0;
            const uint32_t sbn = ((k + 1) & 1) ? sb1 : sb0;
            mbar_expect_tx(mbn, TILE_BYTES);
            tma_load_1d(sbn, ef + (tile + grid) * TILE_FLOATS, TILE_BYTES, mbn);
        }
        // wait current tile's data
        mbar_wait((k & 1) ? mbad1 : mbad0, (k >> 1) & 1);

        float* s = (k & 1) ? buf1 : buf0;
        compute_row(s + lane * ROW, s_cg, warp);   // warps own disjoint columns
        __syncthreads();

        if (tid == 0) {
            fence_async_shared();
            tma_store_1d(out + tile * TILE_FLOATS, (k & 1) ? sb1 : sb0, TILE_BYTES);
            tma_commit();
        }
    }

    // ---- remainder edges (n % TILE == 0 here; kept for generality) ----
    const int rem = n - ntiles * TILE;
    if (rem > 0 && bid == 0) {
        if (tid == 0) tma_wait_all();
        __syncthreads();
        const size_t base = (size_t)ntiles * TILE_FLOATS;
        const int cntf = rem * ROW;
        for (int i = tid; i < cntf; i += THREADS) buf0[i] = ef[base + i];
        __syncthreads();
        if (lane < rem) compute_row(buf0 + lane * ROW, s_cg, warp);
        __syncthreads();
        for (int i = tid; i < cntf; i += THREADS) out[base + i] = buf0[i];
    }

    if (tid == 0) tma_wait_all();   // ensure bulk stores complete before exit
}

extern "C" void kernel_launch(void* const* d_in, const int* in_sizes, int n_in,
                              void* d_out, int out_size) {
    const float* ef    = (const float*)d_in[0];
    const float* cg_ss = (const float*)d_in[1];
    const float* cg_sp = (const float*)d_in[2];
    const float* cg_sd = (const float*)d_in[3];
    const float* cg_pp = (const float*)d_in[4];
    const float* cg_pd = (const float*)d_in[5];
    const float* cg_dd = (const float*)d_in[6];
    float* out = (float*)d_out;

    int n = in_sizes[0] / ROW;
    int ntiles = n / TILE;

    int sms = 148;
    cudaDeviceGetAttribute(&sms, cudaDevAttrMultiProcessorCount, 0);
    int grid = 2 * sms;
    if (ntiles > 0 && grid > ntiles) grid = ntiles;
    if (grid < 1) grid = 1;

    cudaFuncSetAttribute(e3h_kernel, cudaFuncAttributeMaxDynamicSharedMemorySize, SMEM_TOTAL);
    e3h_kernel<<<grid, THREADS, SMEM_TOTAL>>>(ef, cg_ss, cg_sp, cg_sd, cg_pp, cg_pd, cg_dd,
                                              out, n, ntiles);
}

// round 7
// speedup vs baseline: 1.6553x; 1.3187x over previous
#include <cuda_runtime.h>
#include <cstdint>
#include <cstddef>

// E3Hamiltonian: block-diagonal per-edge transform, ROW=282 floats per edge.
// Blocks: ss(off0,np6,m1) sp(off6,np9,m3) sd(off33,np6,m5)
//         pp(off63,np6,m9) pd(off117,np6,m15) dd(off207,np3,m25)

#define ROW 282
#define TILE 32
#define NWC 12
#define THREADS (NWC * 32)                // 384
#define TILE_FLOATS (TILE * ROW)          // 9024
#define TILE_BYTES  (TILE_FLOATS * 4)     // 36096
#define CG_TOTAL 1104
#define SMEM_TOTAL (2 * TILE_BYTES + CG_TOTAL * 4 + 16)  // 76624 B -> 2 CTAs/SM
#define NIN_REGS 36

// ---------------- PTX helpers ----------------
__device__ __forceinline__ uint32_t smem_u32(const void* p) {
    return (uint32_t)__cvta_generic_to_shared(p);
}
__device__ __forceinline__ void mbar_init(uint32_t mbar, uint32_t count) {
    asm volatile("mbarrier.init.shared.b64 [%0], %1;" :: "r"(mbar), "r"(count) : "memory");
}
__device__ __forceinline__ void mbar_expect_tx(uint32_t mbar, uint32_t bytes) {
    asm volatile("mbarrier.arrive.expect_tx.shared::cta.b64 _, [%0], %1;"
                 :: "r"(mbar), "r"(bytes) : "memory");
}
__device__ __forceinline__ void mbar_wait(uint32_t mbar, uint32_t parity) {
    asm volatile(
        "{\n\t.reg .pred P;\n\t"
        "WL_%=:\n\t"
        "mbarrier.try_wait.parity.acquire.cta.shared::cta.b64 P, [%0], %1, 0x989680;\n\t"
        "@P bra.uni WD_%=;\n\t"
        "bra.uni WL_%=;\n\t"
        "WD_%=:\n\t}"
        :: "r"(mbar), "r"(parity) : "memory");
}
__device__ __forceinline__ void tma_load_1d(uint32_t dst_smem, const void* src_gmem,
                                            uint32_t bytes, uint32_t mbar) {
    asm volatile(
        "cp.async.bulk.shared::cta.global.mbarrier::complete_tx::bytes [%0], [%1], %2, [%3];"
        :: "r"(dst_smem), "l"(src_gmem), "r"(bytes), "r"(mbar) : "memory");
}
__device__ __forceinline__ void tma_store_1d(void* dst_gmem, uint32_t src_smem, uint32_t bytes) {
    asm volatile(
        "cp.async.bulk.global.shared::cta.bulk_group [%0], [%1], %2;"
        :: "l"(dst_gmem), "r"(src_smem), "r"(bytes) : "memory");
}
__device__ __forceinline__ void tma_commit() {
    asm volatile("cp.async.bulk.commit_group;" ::: "memory");
}
__device__ __forceinline__ void tma_wait_all() {
    asm volatile("cp.async.bulk.wait_group 0;" ::: "memory");
}
__device__ __forceinline__ void fence_async_shared() {
    asm volatile("fence.proxy.async.shared::cta;" ::: "memory");
}

// ---------------- compute ----------------
// Phase-1 load: in[IB..IB+M) <- r[col..col+M)   (registers)
template <int M, int IB>
__device__ __forceinline__ void loadin(float (&in)[NIN_REGS], const float* __restrict__ r, int col) {
#pragma unroll
    for (int mm = 0; mm < M; mm++) in[IB + mm] = r[col + mm];
}

// Phase-2: outputs j in [J0,J1) of an m x m matvec; inputs from registers,
// cg rows padded to MP (16B aligned, zero-filled), broadcast float4 LDS.
template <int M, int MP, int J0, int J1, int IB>
__device__ __forceinline__ void taskc(const float (&in)[NIN_REGS], float* __restrict__ r,
                                      const float* __restrict__ cg, int col) {
#pragma unroll
    for (int j = J0; j < J1; j++) {
        const float4* c4 = reinterpret_cast<const float4*>(cg + j * MP);
        float acc = 0.f;
#pragma unroll
        for (int k = 0; k < MP / 4; k++) {
            float4 c = c4[k];
            if (4 * k + 0 < M) acc += c.x * in[IB + 4 * k + 0];
            if (4 * k + 1 < M) acc += c.y * in[IB + 4 * k + 1];
            if (4 * k + 2 < M) acc += c.z * in[IB + 4 * k + 2];
            if (4 * k + 3 < M) acc += c.w * in[IB + 4 * k + 3];
        }
        r[col + j] = acc;
    }
}

// cg smem bases (row-major j, rows padded): ss=0(mp4) sp=4(mp4) sd=16(mp8)
// pp=56(mp12) pd=164(mp16) dd=404(mp28)
#define CG_SS (s_cg + 0)
#define CG_SP (s_cg + 4)
#define CG_SD (s_cg + 16)
#define CG_PP (s_cg + 56)
#define CG_PD (s_cg + 164)
#define CG_DD (s_cg + 404)

// 12-warp balanced schedule (364-392 padded FFMA per warp):
// w0: dd@207 j[0,13) + sp@24      w1: dd@207 j[13,25) + sd@33 + sp@15
// w2: dd@232 j[0,13) + sp@27      w3: dd@232 j[13,25) + sd@38 + sp@18
// w4: dd@257 j[0,13) + sp@30      w5: dd@257 j[13,25) + sd@43 + sp@21
// w6: pd@117 + pp@63 + sd@48 + ss@0     w7: pd@132 + pp@72  + sd@53 + ss@1
// w8: pd@147 + pp@81 + sd@58 + ss@2     w9: pd@162 + pp@90  + sp@6  + ss@3
// w10: pd@177 + pp@99 + sp@9 + ss@4     w11: pd@192 + pp@108 + sp@12 + ss@5
__device__ __forceinline__ void load_phase(float (&in)[NIN_REGS], const float* __restrict__ r,
                                           int w) {
    switch (w) {
        case 0:  loadin<25,0>(in,r,207); loadin<3,25>(in,r,24); break;
        case 1:  loadin<25,0>(in,r,207); loadin<5,25>(in,r,33); loadin<3,30>(in,r,15); break;
        case 2:  loadin<25,0>(in,r,232); loadin<3,25>(in,r,27); break;
        case 3:  loadin<25,0>(in,r,232); loadin<5,25>(in,r,38); loadin<3,30>(in,r,18); break;
        case 4:  loadin<25,0>(in,r,257); loadin<3,25>(in,r,30); break;
        case 5:  loadin<25,0>(in,r,257); loadin<5,25>(in,r,43); loadin<3,30>(in,r,21); break;
        case 6:  loadin<15,0>(in,r,117); loadin<9,15>(in,r,63);  loadin<5,24>(in,r,48); loadin<1,29>(in,r,0); break;
        case 7:  loadin<15,0>(in,r,132); loadin<9,15>(in,r,72);  loadin<5,24>(in,r,53); loadin<1,29>(in,r,1); break;
        case 8:  loadin<15,0>(in,r,147); loadin<9,15>(in,r,81);  loadin<5,24>(in,r,58); loadin<1,29>(in,r,2); break;
        case 9:  loadin<15,0>(in,r,162); loadin<9,15>(in,r,90);  loadin<3,24>(in,r,6);  loadin<1,27>(in,r,3); break;
        case 10: loadin<15,0>(in,r,177); loadin<9,15>(in,r,99);  loadin<3,24>(in,r,9);  loadin<1,27>(in,r,4); break;
        default: loadin<15,0>(in,r,192); loadin<9,15>(in,r,108); loadin<3,24>(in,r,12); loadin<1,27>(in,r,5); break;
    }
}

__device__ __forceinline__ void compute_phase(const float (&in)[NIN_REGS], float* __restrict__ r,
                                              const float* __restrict__ s_cg, int w) {
    switch (w) {
        case 0:  taskc<25,28,0,13,0>(in,r,CG_DD,207);  taskc<3,4,0,3,25>(in,r,CG_SP,24); break;
        case 1:  taskc<25,28,13,25,0>(in,r,CG_DD,207); taskc<5,8,0,5,25>(in,r,CG_SD,33); taskc<3,4,0,3,30>(in,r,CG_SP,15); break;
        case 2:  taskc<25,28,0,13,0>(in,r,CG_DD,232);  taskc<3,4,0,3,25>(in,r,CG_SP,27); break;
        case 3:  taskc<25,28,13,25,0>(in,r,CG_DD,232); taskc<5,8,0,5,25>(in,r,CG_SD,38); taskc<3,4,0,3,30>(in,r,CG_SP,18); break;
        case 4:  taskc<25,28,0,13,0>(in,r,CG_DD,257);  taskc<3,4,0,3,25>(in,r,CG_SP,30); break;
        case 5:  taskc<25,28,13,25,0>(in,r,CG_DD,257); taskc<5,8,0,5,25>(in,r,CG_SD,43); taskc<3,4,0,3,30>(in,r,CG_SP,21); break;
        case 6:  taskc<15,16,0,15,0>(in,r,CG_PD,117); taskc<9,12,0,9,15>(in,r,CG_PP,63);  taskc<5,8,0,5,24>(in,r,CG_SD,48); taskc<1,4,0,1,29>(in,r,CG_SS,0); break;
        case 7:  taskc<15,16,0,15,0>(in,r,CG_PD,132); taskc<9,12,0,9,15>(in,r,CG_PP,72);  taskc<5,8,0,5,24>(in,r,CG_SD,53); taskc<1,4,0,1,29>(in,r,CG_SS,1); break;
        case 8:  taskc<15,16,0,15,0>(in,r,CG_PD,147); taskc<9,12,0,9,15>(in,r,CG_PP,81);  taskc<5,8,0,5,24>(in,r,CG_SD,58); taskc<1,4,0,1,29>(in,r,CG_SS,2); break;
        case 9:  taskc<15,16,0,15,0>(in,r,CG_PD,162); taskc<9,12,0,9,15>(in,r,CG_PP,90);  taskc<3,4,0,3,24>(in,r,CG_SP,6);  taskc<1,4,0,1,27>(in,r,CG_SS,3); break;
        case 10: taskc<15,16,0,15,0>(in,r,CG_PD,177); taskc<9,12,0,9,15>(in,r,CG_PP,99);  taskc<3,4,0,3,24>(in,r,CG_SP,9);  taskc<1,4,0,1,27>(in,r,CG_SS,4); break;
        default: taskc<15,16,0,15,0>(in,r,CG_PD,192); taskc<9,12,0,9,15>(in,r,CG_PP,108); taskc<3,4,0,3,24>(in,r,CG_SP,12); taskc<1,4,0,1,27>(in,r,CG_SS,5); break;
    }
}

// fill padded cg (row-major j, rows padded to mp, zero-filled)
__device__ __forceinline__ void fill_cg(float* __restrict__ dst, const float* __restrict__ src,
                                        int m, int mp, int tid) {
    int total = m * mp;
    for (int i = tid; i < total; i += THREADS) {
        int row = i / mp, c = i - row * mp;
        dst[i] = (c < m) ? src[row * m + c] : 0.f;
    }
}

extern __shared__ __align__(128) unsigned char dynsmem[];

__global__ __launch_bounds__(THREADS, 2)
void e3h_kernel(const float* __restrict__ ef,
                const float* __restrict__ cg_ss, const float* __restrict__ cg_sp,
                const float* __restrict__ cg_sd, const float* __restrict__ cg_pp,
                const float* __restrict__ cg_pd, const float* __restrict__ cg_dd,
                float* __restrict__ out, int n, int ntiles) {
    float* buf0 = reinterpret_cast<float*>(dynsmem);
    float* buf1 = buf0 + TILE_FLOATS;
    float* s_cg = buf1 + TILE_FLOATS;
    unsigned long long* mb = reinterpret_cast<unsigned long long*>(s_cg + CG_TOTAL);

    const int tid = threadIdx.x;
    const int lane = tid & 31;
    const int warp = tid >> 5;

    fill_cg(s_cg + 0,   cg_ss, 1, 4,  tid);
    fill_cg(s_cg + 4,   cg_sp, 3, 4,  tid);
    fill_cg(s_cg + 16,  cg_sd, 5, 8,  tid);
    fill_cg(s_cg + 56,  cg_pp, 9, 12, tid);
    fill_cg(s_cg + 164, cg_pd, 15, 16, tid);
    fill_cg(s_cg + 404, cg_dd, 25, 28, tid);

    const uint32_t mbad0 = smem_u32(mb);
    const uint32_t mbad1 = smem_u32(mb + 1);
    const uint32_t sb0 = smem_u32(buf0);
    const uint32_t sb1 = smem_u32(buf1);
    if (tid == 0) { mbar_init(mbad0, 1); mbar_init(mbad1, 1); }
    __syncthreads();

    const int bid = blockIdx.x;
    const int grid = gridDim.x;
    const int cnt = (bid < ntiles) ? (ntiles - bid + grid - 1) / grid : 0;

    if (cnt > 0 && tid == 0) {
        mbar_expect_tx(mbad0, TILE_BYTES);
        tma_load_1d(sb0, ef + (size_t)bid * TILE_FLOATS, TILE_BYTES, mbad0);
    }

    for (int k = 0; k < cnt; k++) {
        const size_t tile = (size_t)bid + (size_t)k * grid;
        if (tid == 0 && k + 1 < cnt) {
            tma_wait_all();   // store of tile k-1 (same buffer) drained
            const uint32_t mbn = ((k + 1) & 1) ? mbad1 : mbad0;
            const uint32_t sbn = ((k + 1) & 1) ? sb1 : sb0;
            mbar_expect_tx(mbn, TILE_BYTES);
            tma_load_1d(sbn, ef + (tile + grid) * TILE_FLOATS, TILE_BYTES, mbn);
        }
        mbar_wait((k & 1) ? mbad1 : mbad0, (k >> 1) & 1);

        float* r = ((k & 1) ? buf1 : buf0) + lane * ROW;

        float in[NIN_REGS];
        load_phase(in, r, warp);          // phase 1: all reads -> registers
        __syncthreads();                  // reads done before any cross-warp write
        compute_phase(in, r, s_cg, warp); // phase 2: FFMA from regs, write smem
        __syncthreads();

        if (tid == 0) {
            fence_async_shared();
            tma_store_1d(out + tile * TILE_FLOATS, (k & 1) ? sb1 : sb0, TILE_BYTES);
            tma_commit();
        }
    }

    // ---- remainder edges (600000 % 32 == 0; kept for generality) ----
    const int rem = n - ntiles * TILE;
    if (rem > 0 && bid == 0) {
        if (tid == 0) tma_wait_all();
        __syncthreads();
        const size_t base = (size_t)ntiles * TILE_FLOATS;
        const int cntf = rem * ROW;
        for (int i = tid; i < cntf; i += THREADS) buf0[i] = ef[base + i];
        __syncthreads();
        float in[NIN_REGS];
        float* r = buf0 + lane * ROW;
        if (lane < rem) load_phase(in, r, warp);
        __syncthreads();
        if (lane < rem) compute_phase(in, r, s_cg, warp);
        __syncthreads();
        for (int i = tid; i < cntf; i += THREADS) out[base + i] = buf0[i];
    }

    if (tid == 0) tma_wait_all();
}

extern "C" void kernel_launch(void* const* d_in, const int* in_sizes, int n_in,
                              void* d_out, int out_size) {
    const float* ef    = (const float*)d_in[0];
    const float* cg_ss = (const float*)d_in[1];
    const float* cg_sp = (const float*)d_in[2];
    const float* cg_sd = (const float*)d_in[3];
    const float* cg_pp = (const float*)d_in[4];
    const float* cg_pd = (const float*)d_in[5];
    const float* cg_dd = (const float*)d_in[6];
    float* out = (float*)d_out;

    int n = in_sizes[0] / ROW;
    int ntiles = n / TILE;

    int sms = 148;
    cudaDeviceGetAttribute(&sms, cudaDevAttrMultiProcessorCount, 0);
    int grid = 2 * sms;
    if (ntiles > 0 && grid > ntiles) grid = ntiles;
    if (grid < 1) grid = 1;

    cudaFuncSetAttribute(e3h_kernel, cudaFuncAttributeMaxDynamicSharedMemorySize, SMEM_TOTAL);
    e3h_kernel<<<grid, THREADS, SMEM_TOTAL>>>(ef, cg_ss, cg_sp, cg_sd, cg_pp, cg_pd, cg_dd,
                                              out, n, ntiles);
}